// round 12
// baseline (speedup 1.0000x reference)
#include <cuda_runtime.h>
#include <cuda_bf16.h>
#include <cstdint>
#include <math.h>

#define NLAYERS 4
#define NQ      256
#define DIM     1024
#define MGAL    51200
#define KC      64                  // k-chunk (elems)
#define NCHUNK  (DIM / KC)          // 16
#define TILE_G  128                 // gallery rows per CTA
#define NTILES  (MGAL / TILE_G)     // 400

// A fragment store: per (layer, chunk): 16 rb * 4 ks * 32 lanes * 4 words = 8192 words (32KB)
#define AW_PER_CHUNK 8192

// SMEM: 2-stage B ring (SW128-swizzled 128B rows) + invnorm
#define BSTAGE  (TILE_G * 128)      // 16384
#define OFF_B   0
#define OFF_INVN (2 * BSTAGE)       // 32768 (128 floats)
#define SMEM_BYTES (OFF_INVN + 512)

__device__ uint32_t g_qA[NLAYERS * NCHUNK * AW_PER_CHUNK];  // bf16 queries, mma-fragment order
__device__ unsigned int g_simmax[NLAYERS * NQ];             // monotone-encoded float max

// ---------------- helpers ----------------
__device__ __forceinline__ uint32_t smem_u32(const void* p) {
    uint32_t a;
    asm("{ .reg .u64 t; cvta.to.shared.u64 t, %1; cvt.u32.u64 %0, t; }" : "=r"(a) : "l"(p));
    return a;
}
#define SWZ(o) ((o) ^ (((o) >> 3) & 0x70))

__device__ __forceinline__ unsigned enc_f(float f) {
    unsigned u = __float_as_uint(f);
    return (u & 0x80000000u) ? ~u : (u | 0x80000000u);
}
__device__ __forceinline__ float dec_f(unsigned u) {
    return __uint_as_float((u & 0x80000000u) ? (u & 0x7fffffffu) : ~u);
}
__device__ __forceinline__ void mma16816(float* d, const uint32_t* a, uint32_t b0, uint32_t b1) {
    asm volatile(
        "mma.sync.aligned.m16n8k16.row.col.f32.bf16.bf16.f32 "
        "{%0,%1,%2,%3}, {%4,%5,%6,%7}, {%8,%9}, {%0,%1,%2,%3};"
        : "+f"(d[0]), "+f"(d[1]), "+f"(d[2]), "+f"(d[3])
        : "r"(a[0]), "r"(a[1]), "r"(a[2]), "r"(a[3]), "r"(b0), "r"(b1));
}
__device__ __forceinline__ void ldmx4(uint32_t* r, uint32_t addr) {
    asm volatile("ldmatrix.sync.aligned.m8n8.x4.shared.b16 {%0,%1,%2,%3}, [%4];"
                 : "=r"(r[0]), "=r"(r[1]), "=r"(r[2]), "=r"(r[3]) : "r"(addr));
}

// ---------------- small kernels ----------------
__global__ void init_kernel() {
    int i = blockIdx.x * blockDim.x + threadIdx.x;
    if (i < NLAYERS * NQ) g_simmax[i] = 0x007FFFFFu;  // enc(-inf)
}

// normalize queries -> bf16, write mma-fragment-ordered layout.
// element (n, k): rb=n>>4, rr=n&15, c=k>>6, ks=(k&63)>>4, kk=k&15
//   lane = (rr&7)*4 + ((kk&7)>>1), word = (rr>>3) + (kk>=8 ? 2 : 0)
__global__ void prep_q_kernel(const float* __restrict__ q) {
    int row = blockIdx.x;                      // l*NQ + n
    int l = row >> 8, n = row & 255;
    const float4 f = reinterpret_cast<const float4*>(q + (size_t)row * DIM)[threadIdx.x];
    __shared__ float red[8];
    float ss = f.x*f.x + f.y*f.y + f.z*f.z + f.w*f.w;
    #pragma unroll
    for (int o = 16; o; o >>= 1) ss += __shfl_xor_sync(~0u, ss, o);
    if ((threadIdx.x & 31) == 0) red[threadIdx.x >> 5] = ss;
    __syncthreads();
    if (threadIdx.x < 8) {
        float s = red[threadIdx.x];
        #pragma unroll
        for (int o = 4; o; o >>= 1) s += __shfl_xor_sync(0xffu, s, o);
        if (threadIdx.x == 0) red[0] = s;
    }
    __syncthreads();
    float inv = 1.0f / fmaxf(sqrtf(red[0]), 1e-8f);

    int k0 = threadIdx.x * 4;
    int c  = k0 >> 6;
    int ks = (k0 & 63) >> 4;
    int kk = k0 & 15;                          // 0,4,8,12
    int rr = n & 15, rb = n >> 4;
    uint32_t base = (uint32_t)((((l * NCHUNK + c) * 16 + rb) * 4 + ks) * 32) * 4;
    int word  = (rr >> 3) + ((kk & 8) ? 2 : 0);
    int lane0 = (rr & 7) * 4 + ((kk & 7) >> 1);
    int lane1 = lane0 + 1;                     // kk+2 pair

    __nv_bfloat162 h0 = __floats2bfloat162_rn(f.x * inv, f.y * inv);
    __nv_bfloat162 h1 = __floats2bfloat162_rn(f.z * inv, f.w * inv);
    g_qA[base + lane0 * 4 + word] = *reinterpret_cast<uint32_t*>(&h0);
    g_qA[base + lane1 * 4 + word] = *reinterpret_cast<uint32_t*>(&h1);
}

__global__ void finalize_kernel(float* __restrict__ out) {
    int n = threadIdx.x;
    float s = 0.0f;
    #pragma unroll
    for (int l = 0; l < NLAYERS; l++) s += dec_f(g_simmax[l * NQ + n]);
    out[n] = 1.0f - s * (1.0f / NLAYERS);
}

// ---------------- main bf16 GEMM + max kernel ----------------
__global__ __launch_bounds__(256, 1)
void gemm_max_kernel(const float* __restrict__ gal) {
    extern __shared__ char smem[];
    const uint32_t sb = smem_u32(smem);
    const int tid = threadIdx.x, wid = tid >> 5, lid = tid & 31;
    const int l  = blockIdx.y;
    const int g0 = blockIdx.x * TILE_G;
    const float* gB = gal + ((size_t)l * MGAL + g0) * DIM;
    const uint32_t* gA = g_qA + (size_t)l * NCHUNK * AW_PER_CHUNK;

    float* invn = reinterpret_cast<float*>(smem + OFF_INVN);
    const int brow = tid >> 1, bhalf = tid & 1;     // B staging: row / 32-col half
    const int wm = wid >> 1, wn = wid & 1;          // warp tile: 64 q x 64 g
    const int rsel = lid & 15, usel = lid >> 4;

    float acc[4][8][4];
    #pragma unroll
    for (int mt = 0; mt < 4; mt++)
        #pragma unroll
        for (int nt = 0; nt < 8; nt++)
            #pragma unroll
            for (int e = 0; e < 4; e++) acc[mt][nt][e] = 0.0f;

    float4 pb[8];
    float ss = 0.0f;

    // prologue: B chunk0 -> regs
    {
        const float* src = gB + (size_t)brow * DIM + bhalf * 32;
        #pragma unroll
        for (int i = 0; i < 8; i++) pb[i] = *reinterpret_cast<const float4*>(src + i * 4);
    }

    for (int c = 0; c < NCHUNK; c++) {
        const uint32_t bufb = sb + OFF_B + (uint32_t)(c & 1) * BSTAGE;

        // ---- stage B chunk c (fp32 -> bf16, SW128), accumulate row sumsq ----
        #pragma unroll
        for (int i = 0; i < 8; i++) {
            float4 f = pb[i];
            ss = fmaf(f.x, f.x, fmaf(f.y, f.y, fmaf(f.z, f.z, fmaf(f.w, f.w, ss))));
            __nv_bfloat162 h0 = __floats2bfloat162_rn(f.x, f.y);
            __nv_bfloat162 h1 = __floats2bfloat162_rn(f.z, f.w);
            uint32_t off = (uint32_t)(brow * 128 + bhalf * 64 + i * 8);
            asm volatile("st.shared.v2.b32 [%0], {%1, %2};"
                         :: "r"(bufb + SWZ(off)),
                            "r"(*reinterpret_cast<uint32_t*>(&h0)),
                            "r"(*reinterpret_cast<uint32_t*>(&h1)) : "memory");
        }
        // ---- issue B LDG for chunk c+1 (completes during compute c) ----
        if (c < NCHUNK - 1) {
            const float* src = gB + (size_t)brow * DIM + (c + 1) * KC + bhalf * 32;
            #pragma unroll
            for (int i = 0; i < 8; i++) pb[i] = *reinterpret_cast<const float4*>(src + i * 4);
        }
        __syncthreads();   // single sync: staging of c visible before compute of c

        // ---- compute: 4 k16-steps; A fragments direct from gmem (pipelined) ----
        const uint32_t* aC = gA + c * AW_PER_CHUNK;
        uint4 af[4];
        #pragma unroll
        for (int mt = 0; mt < 4; mt++)
            af[mt] = *reinterpret_cast<const uint4*>(aC + (((wm * 4 + mt) * 4 + 0) * 32 + lid) * 4);

        #pragma unroll
        for (int ks = 0; ks < 4; ks++) {
            uint4 afn[4];
            if (ks < 3) {
                #pragma unroll
                for (int mt = 0; mt < 4; mt++)
                    afn[mt] = *reinterpret_cast<const uint4*>(
                        aC + (((wm * 4 + mt) * 4 + (ks + 1)) * 32 + lid) * 4);
            }
            uint32_t bfr[4][4];
            #pragma unroll
            for (int g = 0; g < 4; g++) {
                int rowg = wn * 64 + g * 16 + rsel;
                ldmx4(bfr[g], bufb + SWZ((uint32_t)(rowg * 128 + (ks * 2 + usel) * 16)));
            }
            #pragma unroll
            for (int mt = 0; mt < 4; mt++) {
                const uint32_t* a = reinterpret_cast<const uint32_t*>(&af[mt]);
                #pragma unroll
                for (int g = 0; g < 4; g++) {
                    mma16816(acc[mt][2 * g],     a, bfr[g][0], bfr[g][2]);
                    mma16816(acc[mt][2 * g + 1], a, bfr[g][1], bfr[g][3]);
                }
            }
            if (ks < 3) {
                #pragma unroll
                for (int mt = 0; mt < 4; mt++) af[mt] = afn[mt];
            }
        }
        // no second sync: stage->sync->compute ordering makes 2-stage ring safe
    }

    // ---- gallery inverse norms ----
    ss += __shfl_xor_sync(~0u, ss, 1);
    if (bhalf == 0)
        invn[brow] = 1.0f / fmaxf(sqrtf(ss), 1e-8f);
    __syncthreads();

    // ---- epilogue: scale, per-query max, global atomicMax ----
    #pragma unroll
    for (int mt = 0; mt < 4; mt++) {
        float mx0 = -INFINITY, mx1 = -INFINITY;
        #pragma unroll
        for (int nt = 0; nt < 8; nt++) {
            int colb = wn * 64 + nt * 8 + (lid & 3) * 2;
            float i0 = invn[colb], i1 = invn[colb + 1];
            mx0 = fmaxf(mx0, fmaxf(acc[mt][nt][0] * i0, acc[mt][nt][1] * i1));
            mx1 = fmaxf(mx1, fmaxf(acc[mt][nt][2] * i0, acc[mt][nt][3] * i1));
        }
        #pragma unroll
        for (int o = 1; o <= 2; o <<= 1) {
            mx0 = fmaxf(mx0, __shfl_xor_sync(~0u, mx0, o));
            mx1 = fmaxf(mx1, __shfl_xor_sync(~0u, mx1, o));
        }
        if ((lid & 3) == 0) {
            int r = wm * 64 + mt * 16 + (lid >> 2);
            atomicMax(&g_simmax[l * NQ + r],     enc_f(mx0));
            atomicMax(&g_simmax[l * NQ + r + 8], enc_f(mx1));
        }
    }
}

// ---------------- launch ----------------
extern "C" void kernel_launch(void* const* d_in, const int* in_sizes, int n_in,
                              void* d_out, int out_size) {
    const float* q = (const float*)d_in[0];
    const float* g = (const float*)d_in[1];
    if (n_in >= 2 && in_sizes[0] > in_sizes[1]) {
        const float* t = q; q = g; g = t;
    }
    cudaFuncSetAttribute(gemm_max_kernel,
                         cudaFuncAttributeMaxDynamicSharedMemorySize, SMEM_BYTES);

    init_kernel<<<1, NLAYERS * NQ>>>();
    prep_q_kernel<<<NLAYERS * NQ, 256>>>(q);
    gemm_max_kernel<<<dim3(NTILES, NLAYERS), 256, SMEM_BYTES>>>(g);
    finalize_kernel<<<1, NQ>>>((float*)d_out);
}